// round 14
// baseline (speedup 1.0000x reference)
#include <cuda_runtime.h>
#include <cuda_bf16.h>
#include <math.h>
#include <stdint.h>

// Problem constants
#define NN 20000
#define EE 320000
#define BBATCH 16
#define NEG_SLOPE 0.2f
#define M_PAD 20096           // 157 * 128

// ---------------- scratch (static device globals: allocation-free) ----------------
__device__ float g_h[(size_t)M_PAD * 512];   // GEMM output h = x @ W (padded rows)
__device__ __nv_bfloat16 g_ah[(size_t)M_PAD * 512];  // activation hi
__device__ __nv_bfloat16 g_al[(size_t)M_PAD * 512];  // activation lo
__device__ __nv_bfloat16 g_bh[512 * 512];    // weight^T hi  [HF, K]
__device__ __nv_bfloat16 g_bl[512 * 512];    // weight^T lo
__device__ float g_as[NN * 4];
__device__ float g_ad[NN * 4];
__device__ int   g_cnt[NN];
__device__ int   g_rowptr[NN + 1];
__device__ int   g_col[EE];
__device__ int   g_bsum[20];
__device__ int   g_boff[20];
__device__ int   g_flag;

__device__ __forceinline__ float leakyf(float x) { return x > 0.f ? x : NEG_SLOPE * x; }

__device__ __forceinline__ void atomicMaxF(float* addr, float v) {
    if (v >= 0.f) atomicMax((int*)addr, __float_as_int(v));
    else          atomicMin((unsigned int*)addr, __float_as_uint(v));
}

// ================= baseline-PTX tensor-core helpers =================
__device__ __forceinline__ uint32_t smem_u32(const void* p) {
    uint32_t a;
    asm("{ .reg .u64 t; cvta.to.shared.u64 t, %1; cvt.u32.u64 %0, t; }" : "=r"(a) : "l"(p));
    return a;
}
#define CP_COMMIT() asm volatile("cp.async.commit_group;" ::: "memory")
#define CP_WAIT1()  asm volatile("cp.async.wait_group 1;" ::: "memory")
__device__ __forceinline__ void cpa16(uint32_t dst, const void* src) {
    asm volatile("cp.async.cg.shared.global [%0], [%1], 16;" :: "r"(dst), "l"(src) : "memory");
}
__device__ __forceinline__ void ldm4(uint32_t* r, uint32_t addr) {
    asm volatile("ldmatrix.sync.aligned.m8n8.x4.shared.b16 {%0,%1,%2,%3}, [%4];"
                 : "=r"(r[0]), "=r"(r[1]), "=r"(r[2]), "=r"(r[3]) : "r"(addr));
}
__device__ __forceinline__ void mma_bf16(float* d, const uint32_t* a,
                                         uint32_t b0, uint32_t b1) {
    asm volatile("mma.sync.aligned.m16n8k16.row.col.f32.bf16.bf16.f32 "
                 "{%0,%1,%2,%3}, {%4,%5,%6,%7}, {%8,%9}, {%0,%1,%2,%3};"
                 : "+f"(d[0]), "+f"(d[1]), "+f"(d[2]), "+f"(d[3])
                 : "r"(a[0]), "r"(a[1]), "r"(a[2]), "r"(a[3]), "r"(b0), "r"(b1));
}

// ================= bf16 split GEMM (3-term) + fused alpha epilogue ================
// R7-proven config: 3-stage pipeline, interleaved MMA order, 1 CTA/SM.
#define KC 32
#define PITCH 40                 // 80 B rows -> ldmatrix conflict-free
#define TILEB (128 * PITCH * 2)  // 10240 bytes per tile
#define GEMM_SMEM (12 * TILEB)   // 3 stages x 4 tiles = 122880

__global__ __launch_bounds__(256)
void mma_gemm_kernel(const __nv_bfloat16* __restrict__ Ah,
                     const __nv_bfloat16* __restrict__ Al,
                     const __nv_bfloat16* __restrict__ Bh,
                     const __nv_bfloat16* __restrict__ Bl,
                     float* __restrict__ C,
                     const float* __restrict__ asrc,
                     const float* __restrict__ adst,
                     int K, int HF, int H) {
    extern __shared__ __align__(16) __nv_bfloat16 smem[];
    uint32_t s0 = smem_u32(smem);

    int tid  = threadIdx.x;
    int wid  = tid >> 5;
    int lane = tid & 31;
    int m0 = blockIdx.y * 128;
    int n0 = blockIdx.x * 128;
    int wm = (wid & 3) * 32;    // warp M offset
    int wn = (wid >> 2) * 64;   // warp N offset

    float c[2][8][4];
#pragma unroll
    for (int i = 0; i < 2; i++)
#pragma unroll
        for (int j = 0; j < 8; j++)
#pragma unroll
            for (int q = 0; q < 4; q++) c[i][j][q] = 0.f;

    const int KCH = K / KC;

    const __nv_bfloat16* gp0 = Ah + (size_t)m0 * K;
    const __nv_bfloat16* gp1 = Al + (size_t)m0 * K;
    const __nv_bfloat16* gp2 = Bh + (size_t)n0 * K;
    const __nv_bfloat16* gp3 = Bl + (size_t)n0 * K;

    auto load_chunk = [&](int kc, int stage) {
        const __nv_bfloat16* gp[4] = {gp0 + kc * KC, gp1 + kc * KC,
                                      gp2 + kc * KC, gp3 + kc * KC};
#pragma unroll
        for (int kind = 0; kind < 4; kind++) {
            uint32_t base = s0 + (uint32_t)(stage * 4 + kind) * TILEB;
            const __nv_bfloat16* g = gp[kind];
#pragma unroll
            for (int r = 0; r < 2; r++) {
                int i = tid + r * 256;           // 0..511
                int row = i >> 2, seg = i & 3;   // 4 x 16B per 32-elem row
                cpa16(base + (uint32_t)(row * PITCH + seg * 8) * 2,
                      g + (size_t)row * K + seg * 8);
            }
        }
        CP_COMMIT();
    };

    load_chunk(0, 0);
    load_chunk(1, 1);

    int lr = lane & 15, ls = (lane >> 4) * 8;
    for (int t = 0; t < KCH; t++) {
        CP_WAIT1();
        __syncthreads();
        if (t + 2 < KCH) load_chunk(t + 2, (t + 2) % 3);
        else             CP_COMMIT();

        int stage = t % 3;
        uint32_t bAh = s0 + (uint32_t)(stage * 4 + 0) * TILEB;
        uint32_t bAl = s0 + (uint32_t)(stage * 4 + 1) * TILEB;
        uint32_t bBh = s0 + (uint32_t)(stage * 4 + 2) * TILEB;
        uint32_t bBl = s0 + (uint32_t)(stage * 4 + 3) * TILEB;
#pragma unroll
        for (int ks = 0; ks < 2; ks++) {
            int k0 = ks * 16;
            uint32_t ah[2][4], al[2][4], bt[4][4];
#pragma unroll
            for (int mi = 0; mi < 2; mi++)
                ldm4(ah[mi], bAh + (uint32_t)((wm + mi * 16 + lr) * PITCH + k0 + ls) * 2);
#pragma unroll
            for (int mi = 0; mi < 2; mi++)
                ldm4(al[mi], bAl + (uint32_t)((wm + mi * 16 + lr) * PITCH + k0 + ls) * 2);
#pragma unroll
            for (int ni = 0; ni < 4; ni++)
                ldm4(bt[ni], bBh + (uint32_t)((wn + ni * 16 + lr) * PITCH + k0 + ls) * 2);
#pragma unroll
            for (int mi = 0; mi < 2; mi++)
#pragma unroll
                for (int ni = 0; ni < 4; ni++) {
                    mma_bf16(c[mi][ni * 2],     ah[mi], bt[ni][0], bt[ni][2]);
                    mma_bf16(c[mi][ni * 2 + 1], ah[mi], bt[ni][1], bt[ni][3]);
                    mma_bf16(c[mi][ni * 2],     al[mi], bt[ni][0], bt[ni][2]);
                    mma_bf16(c[mi][ni * 2 + 1], al[mi], bt[ni][1], bt[ni][3]);
                }
#pragma unroll
            for (int ni = 0; ni < 4; ni++)
                ldm4(bt[ni], bBl + (uint32_t)((wn + ni * 16 + lr) * PITCH + k0 + ls) * 2);
#pragma unroll
            for (int mi = 0; mi < 2; mi++)
#pragma unroll
                for (int ni = 0; ni < 4; ni++) {
                    mma_bf16(c[mi][ni * 2],     ah[mi], bt[ni][0], bt[ni][2]);
                    mma_bf16(c[mi][ni * 2 + 1], ah[mi], bt[ni][1], bt[ni][3]);
                }
        }
    }
    __syncthreads();   // all compute done; smem reusable

    // ---- alpha epilogue ----
    float* ab = (float*)smem;
    ab[tid] = 0.f;
    __syncthreads();
    {
        float ps[2][2] = {{0.f, 0.f}, {0.f, 0.f}};
        float pd[2][2] = {{0.f, 0.f}, {0.f, 0.f}};
#pragma unroll
        for (int ni = 0; ni < 4; ni++) {
#pragma unroll
            for (int q2 = 0; q2 < 2; q2++) {
                int gc = n0 + wn + ni * 16 + q2 * 8 + (lane & 3) * 2;
                float a0 = asrc[gc], a1 = asrc[gc + 1];
                float d0 = adst[gc], d1 = adst[gc + 1];
#pragma unroll
                for (int mi = 0; mi < 2; mi++) {
                    const float* cc = c[mi][ni * 2 + q2];
                    ps[mi][0] += cc[0] * a0 + cc[1] * a1;
                    pd[mi][0] += cc[0] * d0 + cc[1] * d1;
                    ps[mi][1] += cc[2] * a0 + cc[3] * a1;
                    pd[mi][1] += cc[2] * d0 + cc[3] * d1;
                }
            }
        }
#pragma unroll
        for (int o = 1; o <= 2; o <<= 1)
#pragma unroll
            for (int mi = 0; mi < 2; mi++)
#pragma unroll
                for (int hf = 0; hf < 2; hf++) {
                    ps[mi][hf] += __shfl_xor_sync(0xffffffffu, ps[mi][hf], o);
                    pd[mi][hf] += __shfl_xor_sync(0xffffffffu, pd[mi][hf], o);
                }
        if ((lane & 3) == 0) {
#pragma unroll
            for (int mi = 0; mi < 2; mi++)
#pragma unroll
                for (int hf = 0; hf < 2; hf++) {
                    int row = wm + mi * 16 + (lane >> 2) + hf * 8;
                    atomicAdd(&ab[row * 2],     ps[mi][hf]);
                    atomicAdd(&ab[row * 2 + 1], pd[mi][hf]);
                }
        }
    }
    __syncthreads();
    if (tid < 128) {
        int grow = m0 + tid;
        if (grow < NN) {
            int head = n0 >> 7;
            g_as[grow * H + head] = ab[tid * 2];
            g_ad[grow * H + head] = ab[tid * 2 + 1];
        }
    }

    // ---- C store ----
#pragma unroll
    for (int mi = 0; mi < 2; mi++) {
        int row = m0 + wm + mi * 16 + (lane >> 2);
#pragma unroll
        for (int ni = 0; ni < 8; ni++) {
            int col = n0 + wn + ni * 8 + (lane & 3) * 2;
            *(float2*)&C[(size_t)row * HF + col]       = make_float2(c[mi][ni][0], c[mi][ni][1]);
            *(float2*)&C[(size_t)(row + 8) * HF + col] = make_float2(c[mi][ni][2], c[mi][ni][3]);
        }
    }
}

// ================= fp32 -> bf16 hi/lo conversions =================
__global__ void conv_act_kernel(const float* __restrict__ src, int total) {
    int i = blockIdx.x * blockDim.x + threadIdx.x;
    if (i >= total) return;
    float v = src[i];
    __nv_bfloat16 h = __float2bfloat16(v);
    g_ah[i] = h;
    g_al[i] = __float2bfloat16(v - __bfloat162float(h));
}
// W: [K, HF] -> g_bh/g_bl: [HF, K], tiled transpose
__global__ void conv_wt_kernel(const float* __restrict__ W, int K, int HF) {
    __shared__ float tile[32][33];
    int bx = blockIdx.x * 32;   // HF dim
    int by = blockIdx.y * 32;   // K dim
    int tx = threadIdx.x, ty = threadIdx.y;   // 32 x 8
#pragma unroll
    for (int r = 0; r < 32; r += 8)
        tile[ty + r][tx] = W[(size_t)(by + ty + r) * HF + bx + tx];
    __syncthreads();
#pragma unroll
    for (int r = 0; r < 32; r += 8) {
        float v = tile[tx][ty + r];
        __nv_bfloat16 h = __float2bfloat16(v);
        size_t o = (size_t)(bx + ty + r) * K + by + tx;
        g_bh[o] = h;
        g_bl[o] = __float2bfloat16(v - __bfloat162float(h));
    }
}

// ---------------- CSR build (parallel scan) ----------------
__global__ void zero_cnt_kernel() {
    int i = blockIdx.x * blockDim.x + threadIdx.x;
    if (i < NN) g_cnt[i] = 0;
}
__global__ void count_kernel(const int* __restrict__ ei) {
    int i = blockIdx.x * blockDim.x + threadIdx.x;
    if (i < EE) atomicAdd(&g_cnt[ei[EE + i]], 1);
}
__global__ __launch_bounds__(256) void scan1_kernel() {
    __shared__ int sd[256];
    int b = blockIdx.x, t = threadIdx.x;
    int base = b * 1000 + t * 4;
    int c0 = 0, c1 = 0, c2 = 0, c3 = 0;
    if (t < 250) {
        c0 = g_cnt[base];     c1 = g_cnt[base + 1];
        c2 = g_cnt[base + 2]; c3 = g_cnt[base + 3];
    }
    int s = c0 + c1 + c2 + c3;
    sd[t] = s;
    __syncthreads();
    for (int off = 1; off < 256; off <<= 1) {
        int v = (t >= off) ? sd[t - off] : 0;
        __syncthreads();
        sd[t] += v;
        __syncthreads();
    }
    if (t < 250) {
        int run = sd[t] - s;
        g_rowptr[base]     = run; run += c0; g_cnt[base]     = 0;
        g_rowptr[base + 1] = run; run += c1; g_cnt[base + 1] = 0;
        g_rowptr[base + 2] = run; run += c2; g_cnt[base + 2] = 0;
        g_rowptr[base + 3] = run;            g_cnt[base + 3] = 0;
    }
    if (t == 255) g_bsum[b] = sd[255];
}
__global__ void scan2_kernel() {
    int t = threadIdx.x;
    int own = (t < 20) ? g_bsum[t] : 0;
    int v = own;
    for (int off = 1; off < 32; off <<= 1) {
        int u = __shfl_up_sync(0xffffffffu, v, off);
        if (t >= off) v += u;
    }
    if (t < 20) g_boff[t] = v - own;
    if (t == 19) g_rowptr[NN] = v;
}
__global__ void scan3_kernel() {
    int i = blockIdx.x * blockDim.x + threadIdx.x;
    if (i < NN) g_rowptr[i] += g_boff[i / 1000];
}
__global__ void scatter_kernel(const int* __restrict__ ei) {
    int i = blockIdx.x * blockDim.x + threadIdx.x;
    if (i >= EE) return;
    int dst = ei[EE + i];
    int pos = g_rowptr[dst] + atomicAdd(&g_cnt[dst], 1);
    g_col[pos] = ei[i];
}

// ------- fused single-pass online-softmax aggregation: warp per (dst, head) -------
// mode 0: write bf16 hi/lo split only (layers 1-2, relu)
// mode 1: fused masked global-max-pool into `out` (layer 3, no relu)
__global__ __launch_bounds__(256)
void gat_agg_kernel(const float* __restrict__ bias, int H, int F, int mode,
                    const int* __restrict__ batch, const int* __restrict__ mask,
                    float* __restrict__ out) {
    int gw   = (blockIdx.x * blockDim.x + threadIdx.x) >> 5;
    int lane = threadIdx.x & 31;
    if (gw >= NN * H) return;
    int dst = gw / H, h = gw - dst * H;
    int HF = H * F;

    int r0 = g_rowptr[dst], r1 = g_rowptr[dst + 1];
    float ad_d = g_ad[dst * H + h];
    float m    = leakyf(g_as[dst * H + h] + ad_d);
    float den  = 1.f;

    size_t fofs = (size_t)h * F + lane * 4;
    float4 acc = *(const float4*)&g_h[(size_t)dst * HF + fofs];

    int j = r0;
    for (; j + 4 <= r1; j += 4) {
        int s0 = g_col[j], s1 = g_col[j + 1], s2 = g_col[j + 2], s3 = g_col[j + 3];
        float e0 = leakyf(g_as[s0 * H + h] + ad_d);
        float e1 = leakyf(g_as[s1 * H + h] + ad_d);
        float e2 = leakyf(g_as[s2 * H + h] + ad_d);
        float e3 = leakyf(g_as[s3 * H + h] + ad_d);
        float4 v0 = *(const float4*)&g_h[(size_t)s0 * HF + fofs];
        float4 v1 = *(const float4*)&g_h[(size_t)s1 * HF + fofs];
        float4 v2 = *(const float4*)&g_h[(size_t)s2 * HF + fofs];
        float4 v3 = *(const float4*)&g_h[(size_t)s3 * HF + fofs];
        float mn = fmaxf(fmaxf(m, fmaxf(e0, e1)), fmaxf(e2, e3));
        float sc = __expf(m - mn);
        float w0 = __expf(e0 - mn), w1 = __expf(e1 - mn);
        float w2 = __expf(e2 - mn), w3 = __expf(e3 - mn);
        den = den * sc + (w0 + w1) + (w2 + w3);
        acc.x = acc.x * sc + (w0 * v0.x + w1 * v1.x) + (w2 * v2.x + w3 * v3.x);
        acc.y = acc.y * sc + (w0 * v0.y + w1 * v1.y) + (w2 * v2.y + w3 * v3.y);
        acc.z = acc.z * sc + (w0 * v0.z + w1 * v1.z) + (w2 * v2.z + w3 * v3.z);
        acc.w = acc.w * sc + (w0 * v0.w + w1 * v1.w) + (w2 * v2.w + w3 * v3.w);
        m = mn;
    }
    for (; j < r1; j++) {
        int s0 = g_col[j];
        float e0 = leakyf(g_as[s0 * H + h] + ad_d);
        float4 v0 = *(const float4*)&g_h[(size_t)s0 * HF + fofs];
        float mn = fmaxf(m, e0);
        float sc = __expf(m - mn);
        float w0 = __expf(e0 - mn);
        den = den * sc + w0;
        acc.x = acc.x * sc + w0 * v0.x;
        acc.y = acc.y * sc + w0 * v0.y;
        acc.z = acc.z * sc + w0 * v0.z;
        acc.w = acc.w * sc + w0 * v0.w;
        m = mn;
    }

    float inv = 1.f / den;
    float4 b4 = *(const float4*)&bias[h * F + lane * 4];
    acc.x = acc.x * inv + b4.x;
    acc.y = acc.y * inv + b4.y;
    acc.z = acc.z * inv + b4.z;
    acc.w = acc.w * inv + b4.w;

    if (mode == 0) {
        // relu + bf16 hi/lo split (next layer's GEMM input); no fp32 store
        acc.x = fmaxf(acc.x, 0.f); acc.y = fmaxf(acc.y, 0.f);
        acc.z = fmaxf(acc.z, 0.f); acc.w = fmaxf(acc.w, 0.f);
        size_t oidx = (size_t)dst * HF + fofs;
        __nv_bfloat16 hv[4], lv[4];
        float a[4] = {acc.x, acc.y, acc.z, acc.w};
#pragma unroll
        for (int q = 0; q < 4; q++) {
            hv[q] = __float2bfloat16(a[q]);
            lv[q] = __float2bfloat16(a[q] - __bfloat162float(hv[q]));
        }
        *(uint2*)&g_ah[oidx] = *(uint2*)hv;
        *(uint2*)&g_al[oidx] = *(uint2*)lv;
    } else {
        // fused masked global max pool: no relu, atomics into out[16,128]
        if (!(g_flag && mask[dst] != 0)) {
            float* ob = &out[batch[dst] * 128 + lane * 4];
            atomicMaxF(ob + 0, acc.x);
            atomicMaxF(ob + 1, acc.y);
            atomicMaxF(ob + 2, acc.z);
            atomicMaxF(ob + 3, acc.w);
        }
    }
}

// ---------------- mask flag + pool init ----------------
__global__ void flag_zero_kernel() { g_flag = 0; }
__global__ void flag_set_kernel(const int* __restrict__ mask) {
    int i = blockIdx.x * blockDim.x + threadIdx.x;
    if (i < NN && mask[i] != 0) g_flag = 1;
}
__global__ void pool_init_kernel(float* out) {
    int i = blockIdx.x * blockDim.x + threadIdx.x;
    if (i < BBATCH * 128) out[i] = -1e30f;
}

// ---------------- host side ----------------
static inline int cdiv(int a, int b) { return (a + b - 1) / b; }

static void launch_conv_wt(const float* W, int Fin, int HF, cudaStream_t s) {
    dim3 tgrid(HF / 32, Fin / 32);
    conv_wt_kernel<<<tgrid, dim3(32, 8), 0, s>>>(W, Fin, HF);
}
static void launch_gemm(float* p_h, const float* asrc, const float* adst,
                        int Fin, int HF, int H) {
    __nv_bfloat16 *pah, *pal, *pbh, *pbl;
    cudaGetSymbolAddress((void**)&pah, g_ah);
    cudaGetSymbolAddress((void**)&pal, g_al);
    cudaGetSymbolAddress((void**)&pbh, g_bh);
    cudaGetSymbolAddress((void**)&pbl, g_bl);
    dim3 grid(HF / 128, M_PAD / 128);
    mma_gemm_kernel<<<grid, 256, GEMM_SMEM>>>(pah, pal, pbh, pbl, p_h,
                                              asrc, adst, Fin, HF, H);
}

extern "C" void kernel_launch(void* const* d_in, const int* in_sizes, int n_in,
                              void* d_out, int out_size) {
    const float* x     = (const float*)d_in[0];
    const int*   ei    = (const int*)d_in[1];
    const int*   batch = (const int*)d_in[2];
    const int*   nmask = (const int*)d_in[3];
    // d_in[4] = edge_mask (ignored: GATConv edge_dim=None)
    const float* W1 = (const float*)d_in[5];
    const float* as1 = (const float*)d_in[6];
    const float* ad1 = (const float*)d_in[7];
    const float* b1 = (const float*)d_in[8];
    const float* W2 = (const float*)d_in[9];
    const float* as2 = (const float*)d_in[10];
    const float* ad2 = (const float*)d_in[11];
    const float* b2 = (const float*)d_in[12];
    const float* W3 = (const float*)d_in[13];
    const float* as3 = (const float*)d_in[14];
    const float* ad3 = (const float*)d_in[15];
    const float* b3 = (const float*)d_in[16];

    cudaFuncSetAttribute(mma_gemm_kernel,
                         cudaFuncAttributeMaxDynamicSharedMemorySize, GEMM_SMEM);

    float* p_h = nullptr;
    cudaGetSymbolAddress((void**)&p_h, g_h);
    float* dout = (float*)d_out;

    cudaStream_t aux;
    cudaStreamCreateWithFlags(&aux, cudaStreamNonBlocking);
    cudaEvent_t evFork, evW1, evCsr, evG1, evW2, evG2, evW3;
    cudaEventCreateWithFlags(&evFork, cudaEventDisableTiming);
    cudaEventCreateWithFlags(&evW1,   cudaEventDisableTiming);
    cudaEventCreateWithFlags(&evCsr,  cudaEventDisableTiming);
    cudaEventCreateWithFlags(&evG1,   cudaEventDisableTiming);
    cudaEventCreateWithFlags(&evW2,   cudaEventDisableTiming);
    cudaEventCreateWithFlags(&evG2,   cudaEventDisableTiming);
    cudaEventCreateWithFlags(&evW3,   cudaEventDisableTiming);

    // ---- fork: aux runs conv_wt1 (critical) then CSR build + flag + pool init ----
    cudaEventRecord(evFork, 0);
    cudaStreamWaitEvent(aux, evFork, 0);

    launch_conv_wt(W1, 128, 512, aux);
    cudaEventRecord(evW1, aux);

    zero_cnt_kernel<<<cdiv(NN, 256), 256, 0, aux>>>();
    count_kernel<<<cdiv(EE, 256), 256, 0, aux>>>(ei);
    scan1_kernel<<<20, 256, 0, aux>>>();
    scan2_kernel<<<1, 32, 0, aux>>>();
    scan3_kernel<<<cdiv(NN, 256), 256, 0, aux>>>();
    scatter_kernel<<<cdiv(EE, 256), 256, 0, aux>>>(ei);
    flag_zero_kernel<<<1, 1, 0, aux>>>();
    flag_set_kernel<<<cdiv(NN, 256), 256, 0, aux>>>(nmask);
    pool_init_kernel<<<cdiv(BBATCH * 128, 256), 256, 0, aux>>>(dout);
    cudaEventRecord(evCsr, aux);

    // ---- main chain: layer 1 (conv_act concurrent with conv_wt1 on aux) ----
    conv_act_kernel<<<cdiv(NN * 128, 256), 256>>>(x, NN * 128);
    cudaStreamWaitEvent(0, evW1, 0);
    launch_gemm(p_h, as1, ad1, 128, 512, 4);
    cudaEventRecord(evG1, 0);

    // aux: weight conversion for layer 2, concurrent with agg1
    cudaStreamWaitEvent(aux, evG1, 0);
    launch_conv_wt(W2, 512, 512, aux);
    cudaEventRecord(evW2, aux);

    cudaStreamWaitEvent(0, evCsr, 0);              // CSR ready before aggregation
    gat_agg_kernel<<<cdiv(NN * 4 * 32, 256), 256>>>(b1, 4, 128, 0, batch, nmask, dout);

    // ---- layer 2 ----
    cudaStreamWaitEvent(0, evW2, 0);
    launch_gemm(p_h, as2, ad2, 512, 512, 4);
    cudaEventRecord(evG2, 0);

    cudaStreamWaitEvent(aux, evG2, 0);
    launch_conv_wt(W3, 512, 128, aux);
    cudaEventRecord(evW3, aux);

    gat_agg_kernel<<<cdiv(NN * 4 * 32, 256), 256>>>(b2, 4, 128, 0, batch, nmask, dout);

    // ---- layer 3: agg with fused masked global max pool ----
    cudaStreamWaitEvent(0, evW3, 0);
    launch_gemm(p_h, as3, ad3, 512, 128, 1);
    gat_agg_kernel<<<cdiv(NN * 1 * 32, 256), 256>>>(b3, 1, 128, 1, batch, nmask, dout);

    cudaEventDestroy(evFork); cudaEventDestroy(evW1); cudaEventDestroy(evCsr);
    cudaEventDestroy(evG1);   cudaEventDestroy(evW2);
    cudaEventDestroy(evG2);   cudaEventDestroy(evW3);
    cudaStreamDestroy(aux);
}

// round 15
// speedup vs baseline: 1.3301x; 1.3301x over previous
#include <cuda_runtime.h>
#include <cuda_bf16.h>
#include <math.h>
#include <stdint.h>

// Problem constants
#define NN 20000
#define EE 320000
#define BBATCH 16
#define NEG_SLOPE 0.2f
#define M_PAD 20096           // 157 * 128

// ---------------- scratch (static device globals: allocation-free) ----------------
__device__ float g_h[(size_t)M_PAD * 512];   // GEMM output h = x @ W (padded rows)
__device__ float g_out[(size_t)NN * 512];    // aggregated layer output (layer 3 only read)
__device__ __nv_bfloat16 g_ah[(size_t)M_PAD * 512];  // activation hi
__device__ __nv_bfloat16 g_al[(size_t)M_PAD * 512];  // activation lo
__device__ __nv_bfloat16 g_bh[512 * 512];    // weight^T hi  [HF, K]
__device__ __nv_bfloat16 g_bl[512 * 512];    // weight^T lo
__device__ float g_as[NN * 4];
__device__ float g_ad[NN * 4];
__device__ int   g_cnt[NN];
__device__ int   g_rowptr[NN + 1];
__device__ int   g_col[EE];
__device__ int   g_flag;

__device__ __forceinline__ float leakyf(float x) { return x > 0.f ? x : NEG_SLOPE * x; }

__device__ __forceinline__ void atomicMaxF(float* addr, float v) {
    if (v >= 0.f) atomicMax((int*)addr, __float_as_int(v));
    else          atomicMin((unsigned int*)addr, __float_as_uint(v));
}

// ================= baseline-PTX tensor-core helpers =================
__device__ __forceinline__ uint32_t smem_u32(const void* p) {
    uint32_t a;
    asm("{ .reg .u64 t; cvta.to.shared.u64 t, %1; cvt.u32.u64 %0, t; }" : "=r"(a) : "l"(p));
    return a;
}
#define CP_COMMIT() asm volatile("cp.async.commit_group;" ::: "memory")
#define CP_WAIT1()  asm volatile("cp.async.wait_group 1;" ::: "memory")
__device__ __forceinline__ void cpa16(uint32_t dst, const void* src) {
    asm volatile("cp.async.cg.shared.global [%0], [%1], 16;" :: "r"(dst), "l"(src) : "memory");
}
__device__ __forceinline__ void ldm4(uint32_t* r, uint32_t addr) {
    asm volatile("ldmatrix.sync.aligned.m8n8.x4.shared.b16 {%0,%1,%2,%3}, [%4];"
                 : "=r"(r[0]), "=r"(r[1]), "=r"(r[2]), "=r"(r[3]) : "r"(addr));
}
__device__ __forceinline__ void mma_bf16(float* d, const uint32_t* a,
                                         uint32_t b0, uint32_t b1) {
    asm volatile("mma.sync.aligned.m16n8k16.row.col.f32.bf16.bf16.f32 "
                 "{%0,%1,%2,%3}, {%4,%5,%6,%7}, {%8,%9}, {%0,%1,%2,%3};"
                 : "+f"(d[0]), "+f"(d[1]), "+f"(d[2]), "+f"(d[3])
                 : "r"(a[0]), "r"(a[1]), "r"(a[2]), "r"(a[3]), "r"(b0), "r"(b1));
}

// ================= bf16 split GEMM (3-term) + fused alpha epilogue ================
#define KC 32
#define PITCH 40                 // 80 B rows -> ldmatrix conflict-free
#define TILEB (128 * PITCH * 2)  // 10240 bytes per tile
#define GEMM_SMEM (12 * TILEB)   // 3 stages x 4 tiles = 122880

__global__ __launch_bounds__(256)
void mma_gemm_kernel(const __nv_bfloat16* __restrict__ Ah,
                     const __nv_bfloat16* __restrict__ Al,
                     const __nv_bfloat16* __restrict__ Bh,
                     const __nv_bfloat16* __restrict__ Bl,
                     float* __restrict__ C,
                     const float* __restrict__ asrc,
                     const float* __restrict__ adst,
                     int K, int HF, int H) {
    extern __shared__ __align__(16) __nv_bfloat16 smem[];
    uint32_t s0 = smem_u32(smem);

    int tid  = threadIdx.x;
    int wid  = tid >> 5;
    int lane = tid & 31;
    int m0 = blockIdx.y * 128;
    int n0 = blockIdx.x * 128;
    int wm = (wid & 3) * 32;    // warp M offset
    int wn = (wid >> 2) * 64;   // warp N offset

    float c[2][8][4];
#pragma unroll
    for (int i = 0; i < 2; i++)
#pragma unroll
        for (int j = 0; j < 8; j++)
#pragma unroll
            for (int q = 0; q < 4; q++) c[i][j][q] = 0.f;

    const int KCH = K / KC;

    const __nv_bfloat16* gp0 = Ah + (size_t)m0 * K;
    const __nv_bfloat16* gp1 = Al + (size_t)m0 * K;
    const __nv_bfloat16* gp2 = Bh + (size_t)n0 * K;
    const __nv_bfloat16* gp3 = Bl + (size_t)n0 * K;

    auto load_chunk = [&](int kc, int stage) {
        const __nv_bfloat16* gp[4] = {gp0 + kc * KC, gp1 + kc * KC,
                                      gp2 + kc * KC, gp3 + kc * KC};
#pragma unroll
        for (int kind = 0; kind < 4; kind++) {
            uint32_t base = s0 + (uint32_t)(stage * 4 + kind) * TILEB;
            const __nv_bfloat16* g = gp[kind];
#pragma unroll
            for (int r = 0; r < 2; r++) {
                int i = tid + r * 256;           // 0..511
                int row = i >> 2, seg = i & 3;   // 4 x 16B per 32-elem row
                cpa16(base + (uint32_t)(row * PITCH + seg * 8) * 2,
                      g + (size_t)row * K + seg * 8);
            }
        }
        CP_COMMIT();
    };

    load_chunk(0, 0);
    load_chunk(1, 1);

    int lr = lane & 15, ls = (lane >> 4) * 8;
    for (int t = 0; t < KCH; t++) {
        CP_WAIT1();
        __syncthreads();
        if (t + 2 < KCH) load_chunk(t + 2, (t + 2) % 3);
        else             CP_COMMIT();

        int stage = t % 3;
        uint32_t bAh = s0 + (uint32_t)(stage * 4 + 0) * TILEB;
        uint32_t bAl = s0 + (uint32_t)(stage * 4 + 1) * TILEB;
        uint32_t bBh = s0 + (uint32_t)(stage * 4 + 2) * TILEB;
        uint32_t bBl = s0 + (uint32_t)(stage * 4 + 3) * TILEB;
#pragma unroll
        for (int ks = 0; ks < 2; ks++) {
            int k0 = ks * 16;
            uint32_t ah[2][4], al[2][4], bt[4][4];
#pragma unroll
            for (int mi = 0; mi < 2; mi++)
                ldm4(ah[mi], bAh + (uint32_t)((wm + mi * 16 + lr) * PITCH + k0 + ls) * 2);
#pragma unroll
            for (int mi = 0; mi < 2; mi++)
                ldm4(al[mi], bAl + (uint32_t)((wm + mi * 16 + lr) * PITCH + k0 + ls) * 2);
#pragma unroll
            for (int ni = 0; ni < 4; ni++)
                ldm4(bt[ni], bBh + (uint32_t)((wn + ni * 16 + lr) * PITCH + k0 + ls) * 2);
#pragma unroll
            for (int mi = 0; mi < 2; mi++)
#pragma unroll
                for (int ni = 0; ni < 4; ni++) {
                    mma_bf16(c[mi][ni * 2],     ah[mi], bt[ni][0], bt[ni][2]);
                    mma_bf16(c[mi][ni * 2 + 1], ah[mi], bt[ni][1], bt[ni][3]);
                    mma_bf16(c[mi][ni * 2],     al[mi], bt[ni][0], bt[ni][2]);
                    mma_bf16(c[mi][ni * 2 + 1], al[mi], bt[ni][1], bt[ni][3]);
                }
#pragma unroll
            for (int ni = 0; ni < 4; ni++)
                ldm4(bt[ni], bBl + (uint32_t)((wn + ni * 16 + lr) * PITCH + k0 + ls) * 2);
#pragma unroll
            for (int mi = 0; mi < 2; mi++)
#pragma unroll
                for (int ni = 0; ni < 4; ni++) {
                    mma_bf16(c[mi][ni * 2],     ah[mi], bt[ni][0], bt[ni][2]);
                    mma_bf16(c[mi][ni * 2 + 1], ah[mi], bt[ni][1], bt[ni][3]);
                }
        }
    }
    __syncthreads();   // all compute done; smem reusable

    // ---- alpha epilogue ----
    float* ab = (float*)smem;
    ab[tid] = 0.f;
    __syncthreads();
    {
        float ps[2][2] = {{0.f, 0.f}, {0.f, 0.f}};
        float pd[2][2] = {{0.f, 0.f}, {0.f, 0.f}};
#pragma unroll
        for (int ni = 0; ni < 4; ni++) {
#pragma unroll
            for (int q2 = 0; q2 < 2; q2++) {
                int gc = n0 + wn + ni * 16 + q2 * 8 + (lane & 3) * 2;
                float a0 = asrc[gc], a1 = asrc[gc + 1];
                float d0 = adst[gc], d1 = adst[gc + 1];
#pragma unroll
                for (int mi = 0; mi < 2; mi++) {
                    const float* cc = c[mi][ni * 2 + q2];
                    ps[mi][0] += cc[0] * a0 + cc[1] * a1;
                    pd[mi][0] += cc[0] * d0 + cc[1] * d1;
                    ps[mi][1] += cc[2] * a0 + cc[3] * a1;
                    pd[mi][1] += cc[2] * d0 + cc[3] * d1;
                }
            }
        }
#pragma unroll
        for (int o = 1; o <= 2; o <<= 1)
#pragma unroll
            for (int mi = 0; mi < 2; mi++)
#pragma unroll
                for (int hf = 0; hf < 2; hf++) {
                    ps[mi][hf] += __shfl_xor_sync(0xffffffffu, ps[mi][hf], o);
                    pd[mi][hf] += __shfl_xor_sync(0xffffffffu, pd[mi][hf], o);
                }
        if ((lane & 3) == 0) {
#pragma unroll
            for (int mi = 0; mi < 2; mi++)
#pragma unroll
                for (int hf = 0; hf < 2; hf++) {
                    int row = wm + mi * 16 + (lane >> 2) + hf * 8;
                    atomicAdd(&ab[row * 2],     ps[mi][hf]);
                    atomicAdd(&ab[row * 2 + 1], pd[mi][hf]);
                }
        }
    }
    __syncthreads();
    if (tid < 128) {
        int grow = m0 + tid;
        if (grow < NN) {
            int head = n0 >> 7;
            g_as[grow * H + head] = ab[tid * 2];
            g_ad[grow * H + head] = ab[tid * 2 + 1];
        }
    }

    // ---- C store ----
#pragma unroll
    for (int mi = 0; mi < 2; mi++) {
        int row = m0 + wm + mi * 16 + (lane >> 2);
#pragma unroll
        for (int ni = 0; ni < 8; ni++) {
            int col = n0 + wn + ni * 8 + (lane & 3) * 2;
            *(float2*)&C[(size_t)row * HF + col]       = make_float2(c[mi][ni][0], c[mi][ni][1]);
            *(float2*)&C[(size_t)(row + 8) * HF + col] = make_float2(c[mi][ni][2], c[mi][ni][3]);
        }
    }
}

// ================= fp32 -> bf16 hi/lo conversions =================
__global__ void conv_act_kernel(const float* __restrict__ src, int total) {
    int i = blockIdx.x * blockDim.x + threadIdx.x;
    if (i >= total) return;
    float v = src[i];
    __nv_bfloat16 h = __float2bfloat16(v);
    g_ah[i] = h;
    g_al[i] = __float2bfloat16(v - __bfloat162float(h));
}
// W: [K, HF] -> g_bh/g_bl: [HF, K], tiled transpose
__global__ void conv_wt_kernel(const float* __restrict__ W, int K, int HF) {
    __shared__ float tile[32][33];
    int bx = blockIdx.x * 32;   // HF dim
    int by = blockIdx.y * 32;   // K dim
    int tx = threadIdx.x, ty = threadIdx.y;   // 32 x 8
#pragma unroll
    for (int r = 0; r < 32; r += 8)
        tile[ty + r][tx] = W[(size_t)(by + ty + r) * HF + bx + tx];
    __syncthreads();
#pragma unroll
    for (int r = 0; r < 32; r += 8) {
        float v = tile[tx][ty + r];
        __nv_bfloat16 h = __float2bfloat16(v);
        size_t o = (size_t)(bx + ty + r) * K + by + tx;
        g_bh[o] = h;
        g_bl[o] = __float2bfloat16(v - __bfloat162float(h));
    }
}

// ---------------- CSR build ----------------
__global__ void zero_cnt_kernel() {
    int i = blockIdx.x * blockDim.x + threadIdx.x;
    if (i < NN) g_cnt[i] = 0;
}
__global__ void count_kernel(const int* __restrict__ ei) {
    int i = blockIdx.x * blockDim.x + threadIdx.x;
    if (i < EE) atomicAdd(&g_cnt[ei[EE + i]], 1);
}
// scan also zeroes g_cnt (read then reset), so scatter can reuse it as cursor
__global__ __launch_bounds__(1024) void scan_kernel() {
    __shared__ int sums[1024];
    const int C = 20;
    int t = threadIdx.x;
    int base = t * C;
    int loc[C];
    int s = 0;
    for (int i = 0; i < C; i++) {
        int idx = base + i;
        loc[i] = (idx < NN) ? g_cnt[idx] : 0;
        if (idx < NN) g_cnt[idx] = 0;
        s += loc[i];
    }
    sums[t] = s;
    __syncthreads();
    for (int off = 1; off < 1024; off <<= 1) {
        int v = (t >= off) ? sums[t - off] : 0;
        __syncthreads();
        sums[t] += v;
        __syncthreads();
    }
    int run = (t == 0) ? 0 : sums[t - 1];
    for (int i = 0; i < C; i++) {
        int idx = base + i;
        if (idx < NN) { g_rowptr[idx] = run; run += loc[i]; }
    }
    if (t == 1023) g_rowptr[NN] = run;
}
__global__ void scatter_kernel(const int* __restrict__ ei) {
    int i = blockIdx.x * blockDim.x + threadIdx.x;
    if (i >= EE) return;
    int dst = ei[EE + i];
    int pos = g_rowptr[dst] + atomicAdd(&g_cnt[dst], 1);
    g_col[pos] = ei[i];
}

// ------- fused single-pass online-softmax aggregation: warp per (dst, head) -------
// wsplit=1 (layers 1-2): write ONLY bf16 hi/lo splits (fp32 g_out store is dead).
// wsplit=0 (layer 3): write fp32 g_out (read by pool).
__global__ __launch_bounds__(256)
void gat_agg_kernel(const float* __restrict__ bias, int H, int F, int relu, int wsplit) {
    int gw   = (blockIdx.x * blockDim.x + threadIdx.x) >> 5;
    int lane = threadIdx.x & 31;
    if (gw >= NN * H) return;
    int dst = gw / H, h = gw - dst * H;
    int HF = H * F;

    int r0 = g_rowptr[dst], r1 = g_rowptr[dst + 1];
    float ad_d = g_ad[dst * H + h];
    float m    = leakyf(g_as[dst * H + h] + ad_d);
    float den  = 1.f;

    size_t fofs = (size_t)h * F + lane * 4;
    float4 acc = *(const float4*)&g_h[(size_t)dst * HF + fofs];

    int j = r0;
    for (; j + 4 <= r1; j += 4) {
        int s0 = g_col[j], s1 = g_col[j + 1], s2 = g_col[j + 2], s3 = g_col[j + 3];
        float e0 = leakyf(g_as[s0 * H + h] + ad_d);
        float e1 = leakyf(g_as[s1 * H + h] + ad_d);
        float e2 = leakyf(g_as[s2 * H + h] + ad_d);
        float e3 = leakyf(g_as[s3 * H + h] + ad_d);
        float4 v0 = *(const float4*)&g_h[(size_t)s0 * HF + fofs];
        float4 v1 = *(const float4*)&g_h[(size_t)s1 * HF + fofs];
        float4 v2 = *(const float4*)&g_h[(size_t)s2 * HF + fofs];
        float4 v3 = *(const float4*)&g_h[(size_t)s3 * HF + fofs];
        float mn = fmaxf(fmaxf(m, fmaxf(e0, e1)), fmaxf(e2, e3));
        float sc = __expf(m - mn);
        float w0 = __expf(e0 - mn), w1 = __expf(e1 - mn);
        float w2 = __expf(e2 - mn), w3 = __expf(e3 - mn);
        den = den * sc + (w0 + w1) + (w2 + w3);
        acc.x = acc.x * sc + (w0 * v0.x + w1 * v1.x) + (w2 * v2.x + w3 * v3.x);
        acc.y = acc.y * sc + (w0 * v0.y + w1 * v1.y) + (w2 * v2.y + w3 * v3.y);
        acc.z = acc.z * sc + (w0 * v0.z + w1 * v1.z) + (w2 * v2.z + w3 * v3.z);
        acc.w = acc.w * sc + (w0 * v0.w + w1 * v1.w) + (w2 * v2.w + w3 * v3.w);
        m = mn;
    }
    for (; j < r1; j++) {
        int s0 = g_col[j];
        float e0 = leakyf(g_as[s0 * H + h] + ad_d);
        float4 v0 = *(const float4*)&g_h[(size_t)s0 * HF + fofs];
        float mn = fmaxf(m, e0);
        float sc = __expf(m - mn);
        float w0 = __expf(e0 - mn);
        den = den * sc + w0;
        acc.x = acc.x * sc + w0 * v0.x;
        acc.y = acc.y * sc + w0 * v0.y;
        acc.z = acc.z * sc + w0 * v0.z;
        acc.w = acc.w * sc + w0 * v0.w;
        m = mn;
    }

    float inv = 1.f / den;
    float4 b4 = *(const float4*)&bias[h * F + lane * 4];
    acc.x = acc.x * inv + b4.x;
    acc.y = acc.y * inv + b4.y;
    acc.z = acc.z * inv + b4.z;
    acc.w = acc.w * inv + b4.w;
    if (relu) {
        acc.x = fmaxf(acc.x, 0.f); acc.y = fmaxf(acc.y, 0.f);
        acc.z = fmaxf(acc.z, 0.f); acc.w = fmaxf(acc.w, 0.f);
    }
    size_t oidx = (size_t)dst * HF + fofs;

    if (wsplit) {
        // layers 1-2: only the bf16 split is consumed downstream
        __nv_bfloat16 hv[4], lv[4];
        float a[4] = {acc.x, acc.y, acc.z, acc.w};
#pragma unroll
        for (int q = 0; q < 4; q++) {
            hv[q] = __float2bfloat16(a[q]);
            lv[q] = __float2bfloat16(a[q] - __bfloat162float(hv[q]));
        }
        *(uint2*)&g_ah[oidx] = *(uint2*)hv;
        *(uint2*)&g_al[oidx] = *(uint2*)lv;
    } else {
        // layer 3: pool reads fp32
        *(float4*)&g_out[oidx] = acc;
    }
}

// ---------------- mask flag + pooling ----------------
__global__ void flag_zero_kernel() { g_flag = 0; }
__global__ void flag_set_kernel(const int* __restrict__ mask) {
    int i = blockIdx.x * blockDim.x + threadIdx.x;
    if (i < NN && mask[i] != 0) g_flag = 1;
}
__global__ void pool_init_kernel(float* out) {
    int i = blockIdx.x * blockDim.x + threadIdx.x;
    if (i < BBATCH * 128) out[i] = -1e30f;
}
// grid 157 x 256 threads; sorted batch_id -> block-local running max, flush on boundary
__global__ __launch_bounds__(256)
void pool_kernel(const int* __restrict__ batch,
                 const int* __restrict__ mask,
                 float* __restrict__ out) {
    int f    = threadIdx.x & 127;
    int half = threadIdx.x >> 7;
    int base = blockIdx.x * 128 + half * 64;
    int flag = g_flag;
    int cur = -1;
    float lm = -3e38f;
    int end = base + 64;
    if (end > NN) end = NN;
    for (int n = base; n < end; n++) {
        int b = batch[n];
        if (b != cur) {
            if (cur >= 0) atomicMaxF(&out[cur * 128 + f], lm);
            cur = b;
            lm = -3e38f;
        }
        if (!(flag && mask[n] != 0))
            lm = fmaxf(lm, g_out[(size_t)n * 128 + f]);
    }
    if (cur >= 0) atomicMaxF(&out[cur * 128 + f], lm);
}

// ---------------- host side ----------------
static inline int cdiv(int a, int b) { return (a + b - 1) / b; }

static void launch_conv_wt(const float* W, int Fin, int HF, cudaStream_t s) {
    dim3 tgrid(HF / 32, Fin / 32);
    conv_wt_kernel<<<tgrid, dim3(32, 8), 0, s>>>(W, Fin, HF);
}
static void launch_gemm(float* p_h, const float* asrc, const float* adst,
                        int Fin, int HF, int H) {
    __nv_bfloat16 *pah, *pal, *pbh, *pbl;
    cudaGetSymbolAddress((void**)&pah, g_ah);
    cudaGetSymbolAddress((void**)&pal, g_al);
    cudaGetSymbolAddress((void**)&pbh, g_bh);
    cudaGetSymbolAddress((void**)&pbl, g_bl);
    dim3 grid(HF / 128, M_PAD / 128);
    mma_gemm_kernel<<<grid, 256, GEMM_SMEM>>>(pah, pal, pbh, pbl, p_h,
                                              asrc, adst, Fin, HF, H);
}

extern "C" void kernel_launch(void* const* d_in, const int* in_sizes, int n_in,
                              void* d_out, int out_size) {
    const float* x     = (const float*)d_in[0];
    const int*   ei    = (const int*)d_in[1];
    const int*   batch = (const int*)d_in[2];
    const int*   nmask = (const int*)d_in[3];
    // d_in[4] = edge_mask (ignored: GATConv edge_dim=None)
    const float* W1 = (const float*)d_in[5];
    const float* as1 = (const float*)d_in[6];
    const float* ad1 = (const float*)d_in[7];
    const float* b1 = (const float*)d_in[8];
    const float* W2 = (const float*)d_in[9];
    const float* as2 = (const float*)d_in[10];
    const float* ad2 = (const float*)d_in[11];
    const float* b2 = (const float*)d_in[12];
    const float* W3 = (const float*)d_in[13];
    const float* as3 = (const float*)d_in[14];
    const float* ad3 = (const float*)d_in[15];
    const float* b3 = (const float*)d_in[16];

    cudaFuncSetAttribute(mma_gemm_kernel,
                         cudaFuncAttributeMaxDynamicSharedMemorySize, GEMM_SMEM);

    float* p_h = nullptr;
    cudaGetSymbolAddress((void**)&p_h, g_h);
    float* dout = (float*)d_out;

    cudaStream_t aux;
    cudaStreamCreateWithFlags(&aux, cudaStreamNonBlocking);
    cudaEvent_t evFork, evW1, evCsr, evG1, evW2, evG2, evW3;
    cudaEventCreateWithFlags(&evFork, cudaEventDisableTiming);
    cudaEventCreateWithFlags(&evW1,   cudaEventDisableTiming);
    cudaEventCreateWithFlags(&evCsr,  cudaEventDisableTiming);
    cudaEventCreateWithFlags(&evG1,   cudaEventDisableTiming);
    cudaEventCreateWithFlags(&evW2,   cudaEventDisableTiming);
    cudaEventCreateWithFlags(&evG2,   cudaEventDisableTiming);
    cudaEventCreateWithFlags(&evW3,   cudaEventDisableTiming);

    // ---- fork: aux runs conv_wt1 (critical) then CSR build + flag + pool init ----
    cudaEventRecord(evFork, 0);
    cudaStreamWaitEvent(aux, evFork, 0);

    launch_conv_wt(W1, 128, 512, aux);
    cudaEventRecord(evW1, aux);

    zero_cnt_kernel<<<cdiv(NN, 256), 256, 0, aux>>>();
    count_kernel<<<cdiv(EE, 256), 256, 0, aux>>>(ei);
    scan_kernel<<<1, 1024, 0, aux>>>();            // also re-zeroes g_cnt
    scatter_kernel<<<cdiv(EE, 256), 256, 0, aux>>>(ei);
    flag_zero_kernel<<<1, 1, 0, aux>>>();
    flag_set_kernel<<<cdiv(NN, 256), 256, 0, aux>>>(nmask);
    pool_init_kernel<<<cdiv(BBATCH * 128, 256), 256, 0, aux>>>(dout);
    cudaEventRecord(evCsr, aux);

    // ---- main chain: layer 1 (conv_act runs concurrent with conv_wt1 on aux) ----
    conv_act_kernel<<<cdiv(NN * 128, 256), 256>>>(x, NN * 128);
    cudaStreamWaitEvent(0, evW1, 0);
    launch_gemm(p_h, as1, ad1, 128, 512, 4);
    cudaEventRecord(evG1, 0);

    // aux: weight conversion for layer 2, concurrent with agg1
    cudaStreamWaitEvent(aux, evG1, 0);
    launch_conv_wt(W2, 512, 512, aux);
    cudaEventRecord(evW2, aux);

    cudaStreamWaitEvent(0, evCsr, 0);              // CSR ready before aggregation
    gat_agg_kernel<<<cdiv(NN * 4 * 32, 256), 256>>>(b1, 4, 128, 1, 1);

    // ---- layer 2 ----
    cudaStreamWaitEvent(0, evW2, 0);
    launch_gemm(p_h, as2, ad2, 512, 512, 4);
    cudaEventRecord(evG2, 0);

    cudaStreamWaitEvent(aux, evG2, 0);
    launch_conv_wt(W3, 512, 128, aux);
    cudaEventRecord(evW3, aux);

    gat_agg_kernel<<<cdiv(NN * 4 * 32, 256), 256>>>(b2, 4, 128, 1, 1);

    // ---- layer 3 ----
    cudaStreamWaitEvent(0, evW3, 0);
    launch_gemm(p_h, as3, ad3, 512, 128, 1);
    gat_agg_kernel<<<cdiv(NN * 1 * 32, 256), 256>>>(b3, 1, 128, 0, 0);

    // ---- masked global max pool ----
    pool_kernel<<<M_PAD / 128, 256>>>(batch, nmask, dout);

    cudaEventDestroy(evFork); cudaEventDestroy(evW1); cudaEventDestroy(evCsr);
    cudaEventDestroy(evG1);   cudaEventDestroy(evW2);
    cudaEventDestroy(evG2);   cudaEventDestroy(evW3);
    cudaStreamDestroy(aux);
}

// round 16
// speedup vs baseline: 1.5492x; 1.1647x over previous
#include <cuda_runtime.h>
#include <cuda_fp16.h>
#include <math.h>
#include <stdint.h>

// Problem constants
#define NN 20000
#define EE 320000
#define BBATCH 16
#define NEG_SLOPE 0.2f
#define M_PAD 20096           // 157 * 128

// fp16 two-product split: A*B ~= (255/256)*Ah*Bh + (1/256)*A2*B2
#define SPLIT_S   256.0f
#define SCALE_MID (1.0f / 255.0f)
#define SCALE_FIN (255.0f / 256.0f)

// ---------------- scratch (static device globals: allocation-free) ----------------
__device__ float g_h[(size_t)M_PAD * 512];   // GEMM output h = x @ W (padded rows)
__device__ float g_out[(size_t)NN * 512];    // layer-3 output (read by pool)
__device__ __half g_ah[(size_t)M_PAD * 512]; // activation Ah
__device__ __half g_a2[(size_t)M_PAD * 512]; // activation A2
__device__ __half g_bh[512 * 512];           // weight^T Bh [HF, K]
__device__ __half g_b2[512 * 512];           // weight^T B2
__device__ float g_as[NN * 4];
__device__ float g_ad[NN * 4];
__device__ int   g_cnt[NN];
__device__ int   g_rowptr[NN + 1];
__device__ int   g_col[EE];
__device__ int   g_flag;

__device__ __forceinline__ float leakyf(float x) { return x > 0.f ? x : NEG_SLOPE * x; }

__device__ __forceinline__ void atomicMaxF(float* addr, float v) {
    if (v >= 0.f) atomicMax((int*)addr, __float_as_int(v));
    else          atomicMin((unsigned int*)addr, __float_as_uint(v));
}

// fp16 split: h = fp16(v); A2 = fp16(h + fp16(256*(v-h)))
__device__ __forceinline__ void split16(float v, __half& h, __half& h2) {
    h = __float2half(v);
    float l = v - __half2float(h);
    __half u = __float2half(l * SPLIT_S);
    h2 = __float2half(__half2float(h) + __half2float(u));
}

// ================= baseline-PTX tensor-core helpers =================
__device__ __forceinline__ uint32_t smem_u32(const void* p) {
    uint32_t a;
    asm("{ .reg .u64 t; cvta.to.shared.u64 t, %1; cvt.u32.u64 %0, t; }" : "=r"(a) : "l"(p));
    return a;
}
#define CP_COMMIT() asm volatile("cp.async.commit_group;" ::: "memory")
#define CP_WAIT1()  asm volatile("cp.async.wait_group 1;" ::: "memory")
__device__ __forceinline__ void cpa16(uint32_t dst, const void* src) {
    asm volatile("cp.async.cg.shared.global [%0], [%1], 16;" :: "r"(dst), "l"(src) : "memory");
}
__device__ __forceinline__ void ldm4(uint32_t* r, uint32_t addr) {
    asm volatile("ldmatrix.sync.aligned.m8n8.x4.shared.b16 {%0,%1,%2,%3}, [%4];"
                 : "=r"(r[0]), "=r"(r[1]), "=r"(r[2]), "=r"(r[3]) : "r"(addr));
}
__device__ __forceinline__ void mma_f16(float* d, const uint32_t* a,
                                        uint32_t b0, uint32_t b1) {
    asm volatile("mma.sync.aligned.m16n8k16.row.col.f32.f16.f16.f32 "
                 "{%0,%1,%2,%3}, {%4,%5,%6,%7}, {%8,%9}, {%0,%1,%2,%3};"
                 : "+f"(d[0]), "+f"(d[1]), "+f"(d[2]), "+f"(d[3])
                 : "r"(a[0]), "r"(a[1]), "r"(a[2]), "r"(a[3]), "r"(b0), "r"(b1));
}

// ======= fp16 2-product GEMM: two K-sweeps into one accumulator + alpha epilogue ==
#define KC 32
#define PITCH 40                 // 80 B rows -> ldmatrix conflict-free
#define TILEB (128 * PITCH * 2)  // 10240 bytes per tile
#define GEMM_SMEM (6 * TILEB)    // 3 stages x 2 tiles = 61440

__global__ __launch_bounds__(256)
void mma_gemm_kernel(const __half* __restrict__ Ah,
                     const __half* __restrict__ A2,
                     const __half* __restrict__ Bh,
                     const __half* __restrict__ B2,
                     float* __restrict__ C,
                     const float* __restrict__ asrc,
                     const float* __restrict__ adst,
                     int K, int HF, int H) {
    extern __shared__ __align__(16) __half smem[];
    uint32_t s0 = smem_u32(smem);

    int tid  = threadIdx.x;
    int wid  = tid >> 5;
    int lane = tid & 31;
    int m0 = blockIdx.y * 128;
    int n0 = blockIdx.x * 128;
    int wm = (wid & 3) * 32;    // warp M offset
    int wn = (wid >> 2) * 64;   // warp N offset

    float c[2][8][4];
#pragma unroll
    for (int i = 0; i < 2; i++)
#pragma unroll
        for (int j = 0; j < 8; j++)
#pragma unroll
            for (int q = 0; q < 4; q++) c[i][j][q] = 0.f;

    const int KCH = K / KC;
    const int CT  = 2 * KCH;   // sweep 0: A2*B2, sweep 1: Ah*Bh

    const __half* gpA[2] = {A2 + (size_t)m0 * K, Ah + (size_t)m0 * K};
    const __half* gpB[2] = {B2 + (size_t)n0 * K, Bh + (size_t)n0 * K};

    auto load_chunk = [&](int cidx, int stage) {
        int combo = cidx >= KCH;
        int kc = cidx - (combo ? KCH : 0);
        const __half* gA = gpA[combo] + kc * KC;
        const __half* gB = gpB[combo] + kc * KC;
        uint32_t baseA = s0 + (uint32_t)(stage * 2 + 0) * TILEB;
        uint32_t baseB = s0 + (uint32_t)(stage * 2 + 1) * TILEB;
#pragma unroll
        for (int r = 0; r < 2; r++) {
            int i = tid + r * 256;           // 0..511
            int row = i >> 2, seg = i & 3;   // 4 x 16B per 32-elem row
            uint32_t so = (uint32_t)(row * PITCH + seg * 8) * 2;
            cpa16(baseA + so, gA + (size_t)row * K + seg * 8);
            cpa16(baseB + so, gB + (size_t)row * K + seg * 8);
        }
        CP_COMMIT();
    };

    load_chunk(0, 0);
    load_chunk(1, 1);

    int lr = lane & 15, ls = (lane >> 4) * 8;
    for (int t = 0; t < CT; t++) {
        CP_WAIT1();
        __syncthreads();
        if (t + 2 < CT) load_chunk(t + 2, (t + 2) % 3);
        else            CP_COMMIT();

        if (t == KCH) {   // sweep boundary: acc = P2 -> acc *= s/(1-s)
#pragma unroll
            for (int i = 0; i < 2; i++)
#pragma unroll
                for (int j = 0; j < 8; j++)
#pragma unroll
                    for (int q = 0; q < 4; q++) c[i][j][q] *= SCALE_MID;
        }

        int stage = t % 3;
        uint32_t bA = s0 + (uint32_t)(stage * 2 + 0) * TILEB;
        uint32_t bB = s0 + (uint32_t)(stage * 2 + 1) * TILEB;
#pragma unroll
        for (int ks = 0; ks < 2; ks++) {
            int k0 = ks * 16;
            uint32_t a[2][4], bt[4][4];
#pragma unroll
            for (int mi = 0; mi < 2; mi++)
                ldm4(a[mi], bA + (uint32_t)((wm + mi * 16 + lr) * PITCH + k0 + ls) * 2);
#pragma unroll
            for (int ni = 0; ni < 4; ni++)
                ldm4(bt[ni], bB + (uint32_t)((wn + ni * 16 + lr) * PITCH + k0 + ls) * 2);
#pragma unroll
            for (int mi = 0; mi < 2; mi++)
#pragma unroll
                for (int ni = 0; ni < 4; ni++) {
                    mma_f16(c[mi][ni * 2],     a[mi], bt[ni][0], bt[ni][2]);
                    mma_f16(c[mi][ni * 2 + 1], a[mi], bt[ni][1], bt[ni][3]);
                }
        }
    }
    // final: D = (1-s) * (P1 + s/(1-s)*P2)
#pragma unroll
    for (int i = 0; i < 2; i++)
#pragma unroll
        for (int j = 0; j < 8; j++)
#pragma unroll
            for (int q = 0; q < 4; q++) c[i][j][q] *= SCALE_FIN;

    __syncthreads();   // all compute done; smem reusable

    // ---- alpha epilogue ----
    float* ab = (float*)smem;
    ab[tid] = 0.f;
    __syncthreads();
    {
        float ps[2][2] = {{0.f, 0.f}, {0.f, 0.f}};
        float pd[2][2] = {{0.f, 0.f}, {0.f, 0.f}};
#pragma unroll
        for (int ni = 0; ni < 4; ni++) {
#pragma unroll
            for (int q2 = 0; q2 < 2; q2++) {
                int gc = n0 + wn + ni * 16 + q2 * 8 + (lane & 3) * 2;
                float a0 = asrc[gc], a1 = asrc[gc + 1];
                float d0 = adst[gc], d1 = adst[gc + 1];
#pragma unroll
                for (int mi = 0; mi < 2; mi++) {
                    const float* cc = c[mi][ni * 2 + q2];
                    ps[mi][0] += cc[0] * a0 + cc[1] * a1;
                    pd[mi][0] += cc[0] * d0 + cc[1] * d1;
                    ps[mi][1] += cc[2] * a0 + cc[3] * a1;
                    pd[mi][1] += cc[2] * d0 + cc[3] * d1;
                }
            }
        }
#pragma unroll
        for (int o = 1; o <= 2; o <<= 1)
#pragma unroll
            for (int mi = 0; mi < 2; mi++)
#pragma unroll
                for (int hf = 0; hf < 2; hf++) {
                    ps[mi][hf] += __shfl_xor_sync(0xffffffffu, ps[mi][hf], o);
                    pd[mi][hf] += __shfl_xor_sync(0xffffffffu, pd[mi][hf], o);
                }
        if ((lane & 3) == 0) {
#pragma unroll
            for (int mi = 0; mi < 2; mi++)
#pragma unroll
                for (int hf = 0; hf < 2; hf++) {
                    int row = wm + mi * 16 + (lane >> 2) + hf * 8;
                    atomicAdd(&ab[row * 2],     ps[mi][hf]);
                    atomicAdd(&ab[row * 2 + 1], pd[mi][hf]);
                }
        }
    }
    __syncthreads();
    if (tid < 128) {
        int grow = m0 + tid;
        if (grow < NN) {
            int head = n0 >> 7;
            g_as[grow * H + head] = ab[tid * 2];
            g_ad[grow * H + head] = ab[tid * 2 + 1];
        }
    }

    // ---- C store ----
#pragma unroll
    for (int mi = 0; mi < 2; mi++) {
        int row = m0 + wm + mi * 16 + (lane >> 2);
#pragma unroll
        for (int ni = 0; ni < 8; ni++) {
            int col = n0 + wn + ni * 8 + (lane & 3) * 2;
            *(float2*)&C[(size_t)row * HF + col]       = make_float2(c[mi][ni][0], c[mi][ni][1]);
            *(float2*)&C[(size_t)(row + 8) * HF + col] = make_float2(c[mi][ni][2], c[mi][ni][3]);
        }
    }
}

// ================= fp32 -> fp16 split conversions =================
__global__ void conv_act_kernel(const float* __restrict__ src, int total) {
    int i = blockIdx.x * blockDim.x + threadIdx.x;
    if (i >= total) return;
    __half h, h2;
    split16(src[i], h, h2);
    g_ah[i] = h;
    g_a2[i] = h2;
}
// W: [K, HF] -> g_bh/g_b2: [HF, K], tiled transpose
__global__ void conv_wt_kernel(const float* __restrict__ W, int K, int HF) {
    __shared__ float tile[32][33];
    int bx = blockIdx.x * 32;   // HF dim
    int by = blockIdx.y * 32;   // K dim
    int tx = threadIdx.x, ty = threadIdx.y;   // 32 x 8
#pragma unroll
    for (int r = 0; r < 32; r += 8)
        tile[ty + r][tx] = W[(size_t)(by + ty + r) * HF + bx + tx];
    __syncthreads();
#pragma unroll
    for (int r = 0; r < 32; r += 8) {
        __half h, h2;
        split16(tile[tx][ty + r], h, h2);
        size_t o = (size_t)(bx + ty + r) * K + by + tx;
        g_bh[o] = h;
        g_b2[o] = h2;
    }
}

// ---------------- CSR build ----------------
__global__ void zero_cnt_kernel() {
    int i = blockIdx.x * blockDim.x + threadIdx.x;
    if (i < NN) g_cnt[i] = 0;
}
__global__ void count_kernel(const int* __restrict__ ei) {
    int i = blockIdx.x * blockDim.x + threadIdx.x;
    if (i < EE) atomicAdd(&g_cnt[ei[EE + i]], 1);
}
// scan also zeroes g_cnt (read then reset), so scatter can reuse it as cursor
__global__ __launch_bounds__(1024) void scan_kernel() {
    __shared__ int sums[1024];
    const int C = 20;
    int t = threadIdx.x;
    int base = t * C;
    int loc[C];
    int s = 0;
    for (int i = 0; i < C; i++) {
        int idx = base + i;
        loc[i] = (idx < NN) ? g_cnt[idx] : 0;
        if (idx < NN) g_cnt[idx] = 0;
        s += loc[i];
    }
    sums[t] = s;
    __syncthreads();
    for (int off = 1; off < 1024; off <<= 1) {
        int v = (t >= off) ? sums[t - off] : 0;
        __syncthreads();
        sums[t] += v;
        __syncthreads();
    }
    int run = (t == 0) ? 0 : sums[t - 1];
    for (int i = 0; i < C; i++) {
        int idx = base + i;
        if (idx < NN) { g_rowptr[idx] = run; run += loc[i]; }
    }
    if (t == 1023) g_rowptr[NN] = run;
}
__global__ void scatter_kernel(const int* __restrict__ ei) {
    int i = blockIdx.x * blockDim.x + threadIdx.x;
    if (i >= EE) return;
    int dst = ei[EE + i];
    int pos = g_rowptr[dst] + atomicAdd(&g_cnt[dst], 1);
    g_col[pos] = ei[i];
}

// ------- fused single-pass online-softmax aggregation: warp per (dst, head) -------
// wsplit=1 (layers 1-2): write ONLY fp16 splits. wsplit=0 (layer 3): write fp32 g_out.
__global__ __launch_bounds__(256)
void gat_agg_kernel(const float* __restrict__ bias, int H, int F, int relu, int wsplit) {
    int gw   = (blockIdx.x * blockDim.x + threadIdx.x) >> 5;
    int lane = threadIdx.x & 31;
    if (gw >= NN * H) return;
    int dst = gw / H, h = gw - dst * H;
    int HF = H * F;

    int r0 = g_rowptr[dst], r1 = g_rowptr[dst + 1];
    float ad_d = g_ad[dst * H + h];
    float m    = leakyf(g_as[dst * H + h] + ad_d);
    float den  = 1.f;

    size_t fofs = (size_t)h * F + lane * 4;
    float4 acc = *(const float4*)&g_h[(size_t)dst * HF + fofs];

    int j = r0;
    for (; j + 4 <= r1; j += 4) {
        int s0 = g_col[j], s1 = g_col[j + 1], s2 = g_col[j + 2], s3 = g_col[j + 3];
        float e0 = leakyf(g_as[s0 * H + h] + ad_d);
        float e1 = leakyf(g_as[s1 * H + h] + ad_d);
        float e2 = leakyf(g_as[s2 * H + h] + ad_d);
        float e3 = leakyf(g_as[s3 * H + h] + ad_d);
        float4 v0 = *(const float4*)&g_h[(size_t)s0 * HF + fofs];
        float4 v1 = *(const float4*)&g_h[(size_t)s1 * HF + fofs];
        float4 v2 = *(const float4*)&g_h[(size_t)s2 * HF + fofs];
        float4 v3 = *(const float4*)&g_h[(size_t)s3 * HF + fofs];
        float mn = fmaxf(fmaxf(m, fmaxf(e0, e1)), fmaxf(e2, e3));
        float sc = __expf(m - mn);
        float w0 = __expf(e0 - mn), w1 = __expf(e1 - mn);
        float w2 = __expf(e2 - mn), w3 = __expf(e3 - mn);
        den = den * sc + (w0 + w1) + (w2 + w3);
        acc.x = acc.x * sc + (w0 * v0.x + w1 * v1.x) + (w2 * v2.x + w3 * v3.x);
        acc.y = acc.y * sc + (w0 * v0.y + w1 * v1.y) + (w2 * v2.y + w3 * v3.y);
        acc.z = acc.z * sc + (w0 * v0.z + w1 * v1.z) + (w2 * v2.z + w3 * v3.z);
        acc.w = acc.w * sc + (w0 * v0.w + w1 * v1.w) + (w2 * v2.w + w3 * v3.w);
        m = mn;
    }
    for (; j < r1; j++) {
        int s0 = g_col[j];
        float e0 = leakyf(g_as[s0 * H + h] + ad_d);
        float4 v0 = *(const float4*)&g_h[(size_t)s0 * HF + fofs];
        float mn = fmaxf(m, e0);
        float sc = __expf(m - mn);
        float w0 = __expf(e0 - mn);
        den = den * sc + w0;
        acc.x = acc.x * sc + w0 * v0.x;
        acc.y = acc.y * sc + w0 * v0.y;
        acc.z = acc.z * sc + w0 * v0.z;
        acc.w = acc.w * sc + w0 * v0.w;
        m = mn;
    }

    float inv = 1.f / den;
    float4 b4 = *(const float4*)&bias[h * F + lane * 4];
    acc.x = acc.x * inv + b4.x;
    acc.y = acc.y * inv + b4.y;
    acc.z = acc.z * inv + b4.z;
    acc.w = acc.w * inv + b4.w;
    if (relu) {
        acc.x = fmaxf(acc.x, 0.f); acc.y = fmaxf(acc.y, 0.f);
        acc.z = fmaxf(acc.z, 0.f); acc.w = fmaxf(acc.w, 0.f);
    }
    size_t oidx = (size_t)dst * HF + fofs;

    if (wsplit) {
        __half hv[4], h2v[4];
        float a[4] = {acc.x, acc.y, acc.z, acc.w};
#pragma unroll
        for (int q = 0; q < 4; q++) split16(a[q], hv[q], h2v[q]);
        *(uint2*)&g_ah[oidx] = *(uint2*)hv;
        *(uint2*)&g_a2[oidx] = *(uint2*)h2v;
    } else {
        *(float4*)&g_out[oidx] = acc;
    }
}

// ---------------- mask flag + pooling ----------------
__global__ void flag_zero_kernel() { g_flag = 0; }
__global__ void flag_set_kernel(const int* __restrict__ mask) {
    int i = blockIdx.x * blockDim.x + threadIdx.x;
    if (i < NN && mask[i] != 0) g_flag = 1;
}
__global__ void pool_init_kernel(float* out) {
    int i = blockIdx.x * blockDim.x + threadIdx.x;
    if (i < BBATCH * 128) out[i] = -1e30f;
}
__global__ __launch_bounds__(256)
void pool_kernel(const int* __restrict__ batch,
                 const int* __restrict__ mask,
                 float* __restrict__ out) {
    int f    = threadIdx.x & 127;
    int half = threadIdx.x >> 7;
    int base = blockIdx.x * 128 + half * 64;
    int flag = g_flag;
    int cur = -1;
    float lm = -3e38f;
    int end = base + 64;
    if (end > NN) end = NN;
    for (int n = base; n < end; n++) {
        int b = batch[n];
        if (b != cur) {
            if (cur >= 0) atomicMaxF(&out[cur * 128 + f], lm);
            cur = b;
            lm = -3e38f;
        }
        if (!(flag && mask[n] != 0))
            lm = fmaxf(lm, g_out[(size_t)n * 128 + f]);
    }
    if (cur >= 0) atomicMaxF(&out[cur * 128 + f], lm);
}

// ---------------- host side ----------------
static inline int cdiv(int a, int b) { return (a + b - 1) / b; }

static void launch_conv_wt(const float* W, int Fin, int HF, cudaStream_t s) {
    dim3 tgrid(HF / 32, Fin / 32);
    conv_wt_kernel<<<tgrid, dim3(32, 8), 0, s>>>(W, Fin, HF);
}
static void launch_gemm(float* p_h, const float* asrc, const float* adst,
                        int Fin, int HF, int H) {
    __half *pah, *pa2, *pbh, *pb2;
    cudaGetSymbolAddress((void**)&pah, g_ah);
    cudaGetSymbolAddress((void**)&pa2, g_a2);
    cudaGetSymbolAddress((void**)&pbh, g_bh);
    cudaGetSymbolAddress((void**)&pb2, g_b2);
    dim3 grid(HF / 128, M_PAD / 128);
    mma_gemm_kernel<<<grid, 256, GEMM_SMEM>>>(pah, pa2, pbh, pb2, p_h,
                                              asrc, adst, Fin, HF, H);
}

extern "C" void kernel_launch(void* const* d_in, const int* in_sizes, int n_in,
                              void* d_out, int out_size) {
    const float* x     = (const float*)d_in[0];
    const int*   ei    = (const int*)d_in[1];
    const int*   batch = (const int*)d_in[2];
    const int*   nmask = (const int*)d_in[3];
    // d_in[4] = edge_mask (ignored: GATConv edge_dim=None)
    const float* W1 = (const float*)d_in[5];
    const float* as1 = (const float*)d_in[6];
    const float* ad1 = (const float*)d_in[7];
    const float* b1 = (const float*)d_in[8];
    const float* W2 = (const float*)d_in[9];
    const float* as2 = (const float*)d_in[10];
    const float* ad2 = (const float*)d_in[11];
    const float* b2 = (const float*)d_in[12];
    const float* W3 = (const float*)d_in[13];
    const float* as3 = (const float*)d_in[14];
    const float* ad3 = (const float*)d_in[15];
    const float* b3 = (const float*)d_in[16];

    cudaFuncSetAttribute(mma_gemm_kernel,
                         cudaFuncAttributeMaxDynamicSharedMemorySize, GEMM_SMEM);

    float* p_h = nullptr;
    cudaGetSymbolAddress((void**)&p_h, g_h);
    float* dout = (float*)d_out;

    cudaStream_t aux;
    cudaStreamCreateWithFlags(&aux, cudaStreamNonBlocking);
    cudaEvent_t evFork, evW1, evCsr, evG1, evW2, evG2, evW3;
    cudaEventCreateWithFlags(&evFork, cudaEventDisableTiming);
    cudaEventCreateWithFlags(&evW1,   cudaEventDisableTiming);
    cudaEventCreateWithFlags(&evCsr,  cudaEventDisableTiming);
    cudaEventCreateWithFlags(&evG1,   cudaEventDisableTiming);
    cudaEventCreateWithFlags(&evW2,   cudaEventDisableTiming);
    cudaEventCreateWithFlags(&evG2,   cudaEventDisableTiming);
    cudaEventCreateWithFlags(&evW3,   cudaEventDisableTiming);

    // ---- fork: aux runs conv_wt1 (critical) then CSR build + flag + pool init ----
    cudaEventRecord(evFork, 0);
    cudaStreamWaitEvent(aux, evFork, 0);

    launch_conv_wt(W1, 128, 512, aux);
    cudaEventRecord(evW1, aux);

    zero_cnt_kernel<<<cdiv(NN, 256), 256, 0, aux>>>();
    count_kernel<<<cdiv(EE, 256), 256, 0, aux>>>(ei);
    scan_kernel<<<1, 1024, 0, aux>>>();            // also re-zeroes g_cnt
    scatter_kernel<<<cdiv(EE, 256), 256, 0, aux>>>(ei);
    flag_zero_kernel<<<1, 1, 0, aux>>>();
    flag_set_kernel<<<cdiv(NN, 256), 256, 0, aux>>>(nmask);
    pool_init_kernel<<<cdiv(BBATCH * 128, 256), 256, 0, aux>>>(dout);
    cudaEventRecord(evCsr, aux);

    // ---- main chain: layer 1 (conv_act concurrent with conv_wt1 on aux) ----
    conv_act_kernel<<<cdiv(NN * 128, 256), 256>>>(x, NN * 128);
    cudaStreamWaitEvent(0, evW1, 0);
    launch_gemm(p_h, as1, ad1, 128, 512, 4);
    cudaEventRecord(evG1, 0);

    // aux: weight conversion for layer 2, concurrent with agg1
    cudaStreamWaitEvent(aux, evG1, 0);
    launch_conv_wt(W2, 512, 512, aux);
    cudaEventRecord(evW2, aux);

    cudaStreamWaitEvent(0, evCsr, 0);              // CSR ready before aggregation
    gat_agg_kernel<<<cdiv(NN * 4 * 32, 256), 256>>>(b1, 4, 128, 1, 1);

    // ---- layer 2 ----
    cudaStreamWaitEvent(0, evW2, 0);
    launch_gemm(p_h, as2, ad2, 512, 512, 4);
    cudaEventRecord(evG2, 0);

    cudaStreamWaitEvent(aux, evG2, 0);
    launch_conv_wt(W3, 512, 128, aux);
    cudaEventRecord(evW3, aux);

    gat_agg_kernel<<<cdiv(NN * 4 * 32, 256), 256>>>(b2, 4, 128, 1, 1);

    // ---- layer 3 ----
    cudaStreamWaitEvent(0, evW3, 0);
    launch_gemm(p_h, as3, ad3, 512, 128, 1);
    gat_agg_kernel<<<cdiv(NN * 1 * 32, 256), 256>>>(b3, 1, 128, 0, 0);

    // ---- masked global max pool ----
    pool_kernel<<<M_PAD / 128, 256>>>(batch, nmask, dout);

    cudaEventDestroy(evFork); cudaEventDestroy(evW1); cudaEventDestroy(evCsr);
    cudaEventDestroy(evG1);   cudaEventDestroy(evW2);
    cudaEventDestroy(evG2);   cudaEventDestroy(evW3);
    cudaStreamDestroy(aux);
}